// round 9
// baseline (speedup 1.0000x reference)
#include <cuda_runtime.h>
#include <math.h>
#include <stdint.h>

// ChordalPCWeightTransform — persistent software-pipelined version.
// Math identity (R4): the two per-label rolls cancel on the data and rotate
// only the weight vector:
//   out[b,l,p] = softmax_p( x[b,l,p] * w[(p - root) mod 12] ), p<12; w[12] at p=12
//   root = (row / 12) % 12
//
// R8: persistent CTAs (grid = 148*8) grid-striding over tiles with a
// double-buffered cp.async.cg pipeline: tile i+1 streams into the other smem
// buffer while tile i is computed and stored. Keeps the DRAM read stream
// continuous across the whole kernel (no per-wave cold start / drain).

#define P 13
#define RPB 256
#define TILE_FLOATS (RPB * P)            // 3328 floats = 13312 B (16B aligned)
#define NBUF 2

__device__ __forceinline__ void cp_async16(uint32_t saddr, const void* gptr) {
    asm volatile("cp.async.cg.shared.global [%0], [%1], 16;"
                 :: "r"(saddr), "l"(gptr));
}

__global__ __launch_bounds__(RPB, 8)
void chordal_softmax_pipelined(const float* __restrict__ x,
                               const float* __restrict__ w,
                               float* __restrict__ out,
                               int ntiles)
{
    __shared__ float buf[NBUF][TILE_FLOATS];
    __shared__ float ws[P];

    const int tid = threadIdx.x;
    if (tid < P) ws[tid] = __ldg(&w[tid]);

    const uint32_t s0 = (uint32_t)__cvta_generic_to_shared(&buf[0][0]);
    const uint32_t s1 = (uint32_t)__cvta_generic_to_shared(&buf[1][0]);

    const int t0 = blockIdx.x;
    if (t0 >= ntiles) return;

    // ---- prefetch first tile into buffer 0 ----
    {
        const float4* g = (const float4*)(x + (long long)t0 * TILE_FLOATS);
        cp_async16(s0 + (uint32_t)(tid)       * 16, g + tid);
        cp_async16(s0 + (uint32_t)(tid + 256) * 16, g + tid + 256);
        cp_async16(s0 + (uint32_t)(tid + 512) * 16, g + tid + 512);
        if (tid < 64)
            cp_async16(s0 + (uint32_t)(tid + 768) * 16, g + tid + 768);
    }
    asm volatile("cp.async.commit_group;");

    int bsel = 0;
    for (int t = t0; t < ntiles; t += gridDim.x, bsel ^= 1) {
        // ---- prefetch next tile into the other buffer (may be empty group) ----
        const int tn = t + gridDim.x;
        if (tn < ntiles) {
            const uint32_t sb = bsel ? s0 : s1;       // buffer bsel^1
            const float4* g = (const float4*)(x + (long long)tn * TILE_FLOATS);
            cp_async16(sb + (uint32_t)(tid)       * 16, g + tid);
            cp_async16(sb + (uint32_t)(tid + 256) * 16, g + tid + 256);
            cp_async16(sb + (uint32_t)(tid + 512) * 16, g + tid + 512);
            if (tid < 64)
                cp_async16(sb + (uint32_t)(tid + 768) * 16, g + tid + 768);
        }
        asm volatile("cp.async.commit_group;");       // empty group on last tile
        asm volatile("cp.async.wait_group 1;");       // current tile's data ready
        __syncthreads();

        // ---- per-row weighted softmax (thread owns one row, in place) ----
        float* tile = buf[bsel];
        const int row  = t * RPB + tid;
        const int root = (row / 12) % 12;

        float v[P];
        float m = -INFINITY;
#pragma unroll
        for (int p = 0; p < P; p++) {
            int wi;
            if (p == 12) {
                wi = 12;
            } else {
                wi = p - root;
                if (wi < 0) wi += 12;
            }
            v[p] = tile[tid * P + p] * ws[wi];
            m = fmaxf(m, v[p]);
        }
        float s = 0.0f;
#pragma unroll
        for (int p = 0; p < P; p++) { v[p] = __expf(v[p] - m); s += v[p]; }
        const float r = __frcp_rn(s);
#pragma unroll
        for (int p = 0; p < P; p++) tile[tid * P + p] = v[p] * r;
        __syncthreads();   // all rows written before vectorized readback

        // ---- vectorized streaming store ----
        float4* go = (float4*)(out + (long long)t * TILE_FLOATS);
        const float4* sv = (const float4*)tile;
        __stcs(&go[tid],       sv[tid]);
        __stcs(&go[tid + 256], sv[tid + 256]);
        __stcs(&go[tid + 512], sv[tid + 512]);
        if (tid < 64) __stcs(&go[tid + 768], sv[tid + 768]);
        // No barrier here: buffer bsel is next overwritten by the prefetch at
        // iteration t+2*gridDim.x, which every thread reaches only after both
        // barriers of iteration t+gridDim.x — stores above are long done.
    }
}

extern "C" void kernel_launch(void* const* d_in, const int* in_sizes, int n_in,
                              void* d_out, int out_size)
{
    const float* x = (const float*)d_in[0];   // chordal_pc_vector [65536,144,13]
    const float* w = (const float*)d_in[1];   // scale_degree_weight [13]
    float* out = (float*)d_out;

    const long long total = (long long)in_sizes[0];   // 65536*144*13
    const int ntiles = (int)(total / TILE_FLOATS);    // 36864

    // Ensure full smem carveout so 8 CTAs/SM fit (2*13312B + ws per CTA).
    cudaFuncSetAttribute(chordal_softmax_pipelined,
                         cudaFuncAttributePreferredSharedMemoryCarveout, 100);

    int grid = 148 * 8;                               // persistent: one wave
    if (grid > ntiles) grid = ntiles;

    chordal_softmax_pipelined<<<grid, RPB>>>(x, w, out, ntiles);
}

// round 10
// speedup vs baseline: 1.2434x; 1.2434x over previous
#include <cuda_runtime.h>
#include <math.h>
#include <stdint.h>

// ChordalPCWeightTransform — R9.
// Math identity (R4): the two per-label rolls cancel on the data and rotate
// only the weight vector:
//   out[b,l,p] = softmax_p( x[b,l,p] * w[(p - root) mod 12] ), p<12; w[12] at p=12
//   root = (row / 12) % 12
//
// Structure = R5 (one tile per CTA, eager staging, per-thread 13-wide softmax,
// vectorized streaming store). R9 change: staging uses cp.async.cg
// (global->smem direct, bypassing the register file and L1 data path).

#define P 13
#define RPB 256
#define TILE_FLOATS (RPB * P)            // 3328 floats = 13312 B (16B aligned)

__device__ __forceinline__ void cp_async16(uint32_t saddr, const void* gptr) {
    asm volatile("cp.async.cg.shared.global [%0], [%1], 16;"
                 :: "r"(saddr), "l"(gptr));
}

__global__ __launch_bounds__(RPB)
void chordal_softmax_kernel(const float* __restrict__ x,
                            const float* __restrict__ w,
                            float* __restrict__ out)
{
    __shared__ float tile[TILE_FLOATS];
    __shared__ float ws[P];

    const int tid = threadIdx.x;
    if (tid < P) ws[tid] = __ldg(&w[tid]);

    const long long base = (long long)blockIdx.x * TILE_FLOATS;

    // ---- eager async staging: global -> smem, no register round-trip ----
    {
        const float4* g = (const float4*)(x + base);
        const uint32_t s = (uint32_t)__cvta_generic_to_shared(tile);
        cp_async16(s + (uint32_t)(tid)       * 16, g + tid);
        cp_async16(s + (uint32_t)(tid + 256) * 16, g + tid + 256);
        cp_async16(s + (uint32_t)(tid + 512) * 16, g + tid + 512);
        if (tid < 64)
            cp_async16(s + (uint32_t)(tid + 768) * 16, g + tid + 768);
        asm volatile("cp.async.commit_group;");
        asm volatile("cp.async.wait_group 0;");
    }
    __syncthreads();

    // ---- per-row weighted softmax (thread owns one row, in place) ----
    const int row  = blockIdx.x * RPB + tid;
    const int root = (row / 12) % 12;

    float v[P];
    float m = -INFINITY;
#pragma unroll
    for (int p = 0; p < P; p++) {
        int wi;
        if (p == 12) {
            wi = 12;
        } else {
            wi = p - root;
            if (wi < 0) wi += 12;
        }
        v[p] = tile[tid * P + p] * ws[wi];
        m = fmaxf(m, v[p]);
    }

    float s = 0.0f;
#pragma unroll
    for (int p = 0; p < P; p++) { v[p] = __expf(v[p] - m); s += v[p]; }
    const float r = __frcp_rn(s);

    // This thread overwrites only its own 13 floats — no barrier needed
    // between the reads above and these writes.
#pragma unroll
    for (int p = 0; p < P; p++) tile[tid * P + p] = v[p] * r;
    __syncthreads();   // all rows written before vectorized readback

    // ---- vectorized streaming store: smem -> global ----
    float4* go = (float4*)(out + base);
    const float4* sv = (const float4*)tile;
    __stcs(&go[tid],       sv[tid]);
    __stcs(&go[tid + 256], sv[tid + 256]);
    __stcs(&go[tid + 512], sv[tid + 512]);
    if (tid < 64) __stcs(&go[tid + 768], sv[tid + 768]);
}

extern "C" void kernel_launch(void* const* d_in, const int* in_sizes, int n_in,
                              void* d_out, int out_size)
{
    const float* x = (const float*)d_in[0];   // chordal_pc_vector [65536,144,13]
    const float* w = (const float*)d_in[1];   // scale_degree_weight [13]
    float* out = (float*)d_out;

    const long long total = (long long)in_sizes[0];   // 65536*144*13
    const int nblocks = (int)(total / TILE_FLOATS);   // 36864

    chordal_softmax_kernel<<<nblocks, RPB>>>(x, w, out);
}